// round 6
// baseline (speedup 1.0000x reference)
#include <cuda_runtime.h>
#include <cstdint>

// Problem constants (from reference)
#define E_NUM 128
#define R_NUM 65536
#define S_NUM 100000
#define ER (E_NUM * R_NUM)          // 8,388,608 floats per table

// Interleaved scratch accumulator: scratch[2*(e*R+r)+0] = delta-a,
//                                  scratch[2*(e*R+r)+1] = delta-b
// 2*ER floats = 64 MiB, static device global (no allocation).
//
// INVARIANT: g_scratch is all-zero at entry to every kernel_launch call.
//  - call #1: CUDA zero-initializes __device__ globals at module load.
//  - every call: merge_reset_half reads each scratch element of its half
//    exactly once and stores zero back, restoring the invariant.
// Every call performs identical work -> deterministic & graph-safe.
__device__ float g_scratch[2u * ER];

// ---------------------------------------------------------------------------
// Scatter for estimator half H (e in [64*H, 64*H+64)).
// One thread per 4 (sample, estimator) pairs: int4 sr load covers e0..e0+3 of
// one sample; s is warp-uniform -> da/db broadcast. 4x red.global.add.v2.f32.
// 6.4M RED lanes per half: ~1.29 cyc/lane spread-REDG floor (~31us/half).
// ---------------------------------------------------------------------------
template <int H>
__global__ void __launch_bounds__(256) scatter_half_kernel(
        const int4* __restrict__ sr4,
        const float* __restrict__ da,
        const float* __restrict__ db) {
    int t = blockIdx.x * blockDim.x + threadIdx.x;   // [0, S*16)
    if (t >= S_NUM * 16) return;
    int s = t >> 4;                                  // sample (warp spans 2)
    int j = t & 15;                                  // int4 slot within half
    int4 r = __ldg(sr4 + s * 32 + H * 16 + j);       // coalesced 256B chunks
    float va = __ldg(da + s);
    float vb = __ldg(db + s);
    int e0 = (H * 16 + j) * 4;                       // first estimator of the 4

    float* base = g_scratch + 2u * (size_t)e0 * R_NUM;
    float* p0 = base + 2u * (size_t)r.x;
    float* p1 = base + 2u * ((size_t)R_NUM + (size_t)r.y);
    float* p2 = base + 2u * (2u * (size_t)R_NUM + (size_t)r.z);
    float* p3 = base + 2u * (3u * (size_t)R_NUM + (size_t)r.w);
    asm volatile("red.global.add.v2.f32 [%0], {%1, %2};" :: "l"(p0), "f"(va), "f"(vb) : "memory");
    asm volatile("red.global.add.v2.f32 [%0], {%1, %2};" :: "l"(p1), "f"(va), "f"(vb) : "memory");
    asm volatile("red.global.add.v2.f32 [%0], {%1, %2};" :: "l"(p2), "f"(va), "f"(vb) : "memory");
    asm volatile("red.global.add.v2.f32 [%0], {%1, %2};" :: "l"(p3), "f"(va), "f"(vb) : "memory");
}

// ---------------------------------------------------------------------------
// Merge + reset for half H: out[0][half] = a + scratch.a, out[1][half] = b +
// scratch.b (deinterleave), then zero the scratch half (restores invariant).
// Runs concurrently with the OTHER half's scatter -> its DRAM traffic hides
// under the scatter's LSU-bound phase (DRAM ~33% busy there).
// ---------------------------------------------------------------------------
template <int H>
__global__ void __launch_bounds__(256) merge_reset_half_kernel(
        const float4* __restrict__ a,
        const float4* __restrict__ b,
        float4* __restrict__ out) {
    int i = blockIdx.x * blockDim.x + threadIdx.x;   // [0, ER/8) exact
    int gi = H * (ER / 8) + i;                       // float4 index in tables
    float4* s4 = reinterpret_cast<float4*>(g_scratch);
    float4 p0 = s4[2 * gi + 0];  // {a0,b0,a1,b1}
    float4 p1 = s4[2 * gi + 1];  // {a2,b2,a3,b3}
    float4 va = __ldcs(a + gi);
    float4 vb = __ldcs(b + gi);
    __stcs(out + gi,
           make_float4(va.x + p0.x, va.y + p0.z, va.z + p1.x, va.w + p1.z));
    __stcs(out + ER / 4 + gi,
           make_float4(vb.x + p0.y, vb.y + p0.w, vb.z + p1.y, vb.w + p1.w));
    const float4 z = make_float4(0.f, 0.f, 0.f, 0.f);
    s4[2 * gi + 0] = z;
    s4[2 * gi + 1] = z;
}

extern "C" void kernel_launch(void* const* d_in, const int* in_sizes, int n_in,
                              void* d_out, int out_size) {
    const float* a  = (const float*)d_in[0];          // [E, R]
    const float* b  = (const float*)d_in[1];          // [E, R]
    const int*   sr = (const int*)d_in[2];            // [S, E]
    const float* da = (const float*)d_in[3];          // [S]
    const float* db = (const float*)d_in[4];          // [S]
    float* out = (float*)d_out;                       // [2, E, R]
    const int4* sr4 = (const int4*)sr;

    // One-time resources, created on the (uncaptured) correctness call.
    // Streams/events are host objects — no device memory is allocated.
    static cudaStream_t s2 = [] {
        cudaStream_t s; cudaStreamCreateWithFlags(&s, cudaStreamNonBlocking);
        return s;
    }();
    static cudaEvent_t ev0 = [] {
        cudaEvent_t e; cudaEventCreateWithFlags(&e, cudaEventDisableTiming);
        return e;
    }();
    static cudaEvent_t evm = [] {
        cudaEvent_t e; cudaEventCreateWithFlags(&e, cudaEventDisableTiming);
        return e;
    }();

    const int SC_BLOCKS = S_NUM * 16 / 256;           // 6250 exact
    const int MG_BLOCKS = ER / 8 / 256;               // 4096 exact

    // d : scatter_e0 ─ev0─► scatter_e1 ─► merge_e1 ─wait(evm)─ done
    // s2:           └────► merge_e0 ─evm┘
    scatter_half_kernel<0><<<SC_BLOCKS, 256>>>(sr4, da, db);
    cudaEventRecord(ev0, 0);

    cudaStreamWaitEvent(s2, ev0, 0);
    merge_reset_half_kernel<0><<<MG_BLOCKS, 256, 0, s2>>>(
        (const float4*)a, (const float4*)b, (float4*)out);
    cudaEventRecord(evm, s2);

    scatter_half_kernel<1><<<SC_BLOCKS, 256>>>(sr4, da, db);
    merge_reset_half_kernel<1><<<MG_BLOCKS, 256>>>(
        (const float4*)a, (const float4*)b, (float4*)out);

    cudaStreamWaitEvent(0, evm, 0);                   // join fork
}

// round 7
// speedup vs baseline: 1.1033x; 1.1033x over previous
#include <cuda_runtime.h>
#include <cstdint>

// Problem constants (from reference)
#define E_NUM 128
#define R_NUM 65536
#define S_NUM 100000
#define ER (E_NUM * R_NUM)          // 8,388,608 floats per table

// Interleaved scratch accumulator: scratch[2*(e*R+r)+0] = delta-a,
//                                  scratch[2*(e*R+r)+1] = delta-b
// 2*ER floats = 64 MiB, static device global (no allocation).
__device__ float g_scratch[2u * ER];

// ---------------------------------------------------------------------------
// Kernel 1: scatter-add. One thread per 4 (sample, estimator) pairs.
// int4 load of sr covers e..e+3 of the same sample; s is warp-uniform so
// da[s]/db[s] are broadcast loads. 4x red.global.add.v2.f32 — the 12.8M RED
// lanes sit exactly at the spread-REDG floor (1.29 cyc/lane per SM): 62 us.
// ---------------------------------------------------------------------------
__global__ void __launch_bounds__(256) scatter_v2x4_kernel(
        const int4* __restrict__ sr4,
        const float* __restrict__ da,
        const float* __restrict__ db) {
    int t = blockIdx.x * blockDim.x + threadIdx.x;   // [0, S*E/4) exact grid
    int e0 = (t & 31) << 2;                          // e = e0..e0+3
    int s  = t >> 5;                                 // warp-uniform
    int4 r = __ldg(sr4 + t);                         // coalesced 16B
    float va = __ldg(da + s);                        // broadcast
    float vb = __ldg(db + s);

    float* base = g_scratch + 2u * (size_t)e0 * R_NUM;
    float* p0 = base + 2u * (size_t)r.x;
    float* p1 = base + 2u * ((size_t)R_NUM + (size_t)r.y);
    float* p2 = base + 2u * (2u * (size_t)R_NUM + (size_t)r.z);
    float* p3 = base + 2u * (3u * (size_t)R_NUM + (size_t)r.w);
    asm volatile("red.global.add.v2.f32 [%0], {%1, %2};" :: "l"(p0), "f"(va), "f"(vb) : "memory");
    asm volatile("red.global.add.v2.f32 [%0], {%1, %2};" :: "l"(p1), "f"(va), "f"(vb) : "memory");
    asm volatile("red.global.add.v2.f32 [%0], {%1, %2};" :: "l"(p2), "f"(va), "f"(vb) : "memory");
    asm volatile("red.global.add.v2.f32 [%0], {%1, %2};" :: "l"(p3), "f"(va), "f"(vb) : "memory");
}

// ---------------------------------------------------------------------------
// Kernel 2: merge: out[0] = a + scratch.a (deinterleave), out[1] = b + scratch.b
// scratch reads are L2-warm from the scatter; a/b cold one-shot reads use
// __ldcs; out writes use __stcs. Measured at ~8 TB/s aggregate — at roofline.
// ---------------------------------------------------------------------------
__global__ void __launch_bounds__(256) merge_kernel(
        const float4* __restrict__ a,
        const float4* __restrict__ b,
        float4* __restrict__ out) {
    int i = blockIdx.x * blockDim.x + threadIdx.x;   // [0, ER/4) exact grid
    const float4* s4 = reinterpret_cast<const float4*>(g_scratch);
    float4 p0 = s4[2 * i + 0];   // {a0,b0,a1,b1}
    float4 p1 = s4[2 * i + 1];   // {a2,b2,a3,b3}
    float4 va = __ldcs(a + i);
    float4 vb = __ldcs(b + i);
    __stcs(out + i,
           make_float4(va.x + p0.x, va.y + p0.z, va.z + p1.x, va.w + p1.z));
    __stcs(out + ER / 4 + i,
           make_float4(vb.x + p0.y, vb.y + p0.w, vb.z + p1.y, vb.w + p1.w));
}

extern "C" void kernel_launch(void* const* d_in, const int* in_sizes, int n_in,
                              void* d_out, int out_size) {
    const float* a  = (const float*)d_in[0];          // [E, R]
    const float* b  = (const float*)d_in[1];          // [E, R]
    const int*   sr = (const int*)d_in[2];            // [S, E]
    const float* da = (const float*)d_in[3];          // [S]
    const float* db = (const float*)d_in[4];          // [S]
    float* out = (float*)d_out;                       // [2, E, R]

    // Resolve the scratch symbol's device address once (host-side query,
    // no allocation). Captured calls only see cudaMemsetAsync below.
    static void* scratch_ptr = [] {
        void* p = nullptr;
        cudaGetSymbolAddress(&p, g_scratch);
        return p;
    }();

    // Phase 1: zero scratch via a memset node (driver fill path).
    cudaMemsetAsync(scratch_ptr, 0, sizeof(float) * 2u * ER, 0);

    // Phase 2: scatter (3.2M threads, 4 pairs each; 12500 blocks exact)
    scatter_v2x4_kernel<<<S_NUM * E_NUM / 4 / 256, 256>>>((const int4*)sr, da, db);

    // Phase 3: merge + deinterleave into output (2,097,152 / 256 = 8192 blocks)
    merge_kernel<<<ER / 4 / 256, 256>>>((const float4*)a, (const float4*)b,
                                        (float4*)out);
}